// round 1
// baseline (speedup 1.0000x reference)
#include <cuda_runtime.h>
#include <cuda_bf16.h>
#include <math.h>

// Problem constants
#define NB   8
#define FF   16
#define SS   196
#define DD   1024
#define HH   8
#define HD   128
#define LL   (1 + FF * SS)      // 3137
#define MM   (NB * LL)          // 25096
#define NH   (NB * HH)          // 64

// ---------------------------------------------------------------------------
// Scratch (allocation-free rule: __device__ globals)
// ---------------------------------------------------------------------------
__device__ float g_tmp0[(size_t)MM * DD];   // x@W_in + b_in  (also reused for LN2 output)
__device__ float g_xln [(size_t)MM * DD];   // LN1 output
__device__ float g_q   [(size_t)MM * DD];   // head-split (nh, L, HD)
__device__ float g_k   [(size_t)MM * DD];
__device__ float g_v   [(size_t)MM * DD];
__device__ float g_attn[(size_t)MM * DD];   // head-split (nh, L, HD)

// ---------------------------------------------------------------------------
// GEMM: C[M,1024] = A[M,1024] @ B[1024,1024] (+bias)   MODE 0: row-major out
//                                                      MODE 1: head-split scatter
// ---------------------------------------------------------------------------
#define BM 128
#define BN 128
#define BK 16
#define TM 8
#define TN 8

template<int MODE>
__global__ void __launch_bounds__(256)
gemm_kernel(const float* __restrict__ A, const float* __restrict__ B,
            const float* __restrict__ bias, float* __restrict__ C, int M)
{
    __shared__ float As[BK][BM];   // transposed: As[k][m]
    __shared__ float Bs[BK][BN];

    const int K = 1024, Ncol = 1024;
    const int bm = blockIdx.y * BM;
    const int bn = blockIdx.x * BN;
    const int tid = threadIdx.x;
    const int tr = tid / 16;
    const int tc = tid % 16;

    float acc[TM][TN];
#pragma unroll
    for (int i = 0; i < TM; i++)
#pragma unroll
        for (int j = 0; j < TN; j++) acc[i][j] = 0.f;

    for (int k0 = 0; k0 < K; k0 += BK) {
#pragma unroll
        for (int t = 0; t < 2; t++) {
            int idx = tid + t * 256;
            // A tile: 128 rows x 16 k, as float4 along k
            int arow = idx >> 2;
            int k4   = (idx & 3) * 4;
            float4 av = make_float4(0.f, 0.f, 0.f, 0.f);
            int grow = bm + arow;
            if (grow < M)
                av = *reinterpret_cast<const float4*>(&A[(size_t)grow * K + k0 + k4]);
            As[k4 + 0][arow] = av.x;
            As[k4 + 1][arow] = av.y;
            As[k4 + 2][arow] = av.z;
            As[k4 + 3][arow] = av.w;
            // B tile: 16 k x 128 cols, float4 along n
            int bkrow = idx >> 5;
            int bc4   = (idx & 31) * 4;
            float4 bv = *reinterpret_cast<const float4*>(&B[(size_t)(k0 + bkrow) * Ncol + bn + bc4]);
            *reinterpret_cast<float4*>(&Bs[bkrow][bc4]) = bv;
        }
        __syncthreads();

#pragma unroll
        for (int kk = 0; kk < BK; kk++) {
            float a[TM], b[TN];
#pragma unroll
            for (int i = 0; i < TM; i++) a[i] = As[kk][tr * TM + i];
#pragma unroll
            for (int j = 0; j < TN; j++) b[j] = Bs[kk][tc * TN + j];
#pragma unroll
            for (int i = 0; i < TM; i++)
#pragma unroll
                for (int j = 0; j < TN; j++)
                    acc[i][j] += a[i] * b[j];
        }
        __syncthreads();
    }

#pragma unroll
    for (int i = 0; i < TM; i++) {
        int row = bm + tr * TM + i;
        if (row >= M) continue;
        if (MODE == 0) {
#pragma unroll
            for (int j = 0; j < TN; j++) {
                int col = bn + tc * TN + j;
                float vv = acc[i][j];
                if (bias) vv += bias[col];
                C[(size_t)row * Ncol + col] = vv;
            }
        } else {
            int b_ = row / LL;
            int l_ = row - b_ * LL;
#pragma unroll
            for (int j = 0; j < TN; j++) {
                int col = bn + tc * TN + j;
                int h = col >> 7;
                int d = col & 127;
                C[(((size_t)(b_ * HH + h)) * LL + l_) * HD + d] = acc[i][j];
            }
        }
    }
}

// ---------------------------------------------------------------------------
// LayerNorm over D=1024. GATHER=0: row-major input. GATHER=1: head-merge input
// from (nh, L, HD) layout. Output always row-major [M, D].
// ---------------------------------------------------------------------------
template<int GATHER>
__global__ void __launch_bounds__(256)
ln_kernel(const float* __restrict__ in, const float* __restrict__ g,
          const float* __restrict__ beta, float* __restrict__ out)
{
    const int row = blockIdx.x;
    const int tid = threadIdx.x;
    int b_ = 0, l_ = 0;
    if (GATHER) { b_ = row / LL; l_ = row - b_ * LL; }

    float v[4];
    float s = 0.f, ss = 0.f;
#pragma unroll
    for (int i = 0; i < 4; i++) {
        int c = i * 256 + tid;
        float x;
        if (GATHER) {
            int h = c >> 7, d = c & 127;
            x = in[(((size_t)(b_ * HH + h)) * LL + l_) * HD + d];
        } else {
            x = in[(size_t)row * DD + c];
        }
        v[i] = x; s += x; ss += x * x;
    }

    __shared__ float rs[32], rss[32];
#pragma unroll
    for (int o = 16; o > 0; o >>= 1) {
        s  += __shfl_xor_sync(0xffffffffu, s,  o);
        ss += __shfl_xor_sync(0xffffffffu, ss, o);
    }
    int warp = tid >> 5, lane = tid & 31;
    if (lane == 0) { rs[warp] = s; rss[warp] = ss; }
    __syncthreads();
    if (warp == 0) {
        float s2  = (lane < 8) ? rs[lane]  : 0.f;
        float ss2 = (lane < 8) ? rss[lane] : 0.f;
#pragma unroll
        for (int o = 4; o > 0; o >>= 1) {
            s2  += __shfl_xor_sync(0xffffffffu, s2,  o);
            ss2 += __shfl_xor_sync(0xffffffffu, ss2, o);
        }
        if (lane == 0) { rs[0] = s2; rss[0] = ss2; }
    }
    __syncthreads();
    s = rs[0]; ss = rss[0];

    float mean = s * (1.f / 1024.f);
    float var  = ss * (1.f / 1024.f) - mean * mean;
    float rstd = rsqrtf(var + 1e-5f);

#pragma unroll
    for (int i = 0; i < 4; i++) {
        int c = i * 256 + tid;
        out[(size_t)row * DD + c] = (v[i] - mean) * rstd * g[c] + beta[c];
    }
}

// ---------------------------------------------------------------------------
// Temporal attention (att_type == 1). One block per (bh, s).
// 16 queries (frames) x 17 keys (feat + 16 frames) x HD=128.
// NOTE: the reference's jnp.tile pairs block (bh,s) with feat_k/feat_v of
// head index (bh*S + s) % nh — we replicate that exactly.
// ---------------------------------------------------------------------------
__global__ void __launch_bounds__(256)
attn_temporal(const float* __restrict__ q, const float* __restrict__ k,
              const float* __restrict__ v, float* __restrict__ out,
              const int* __restrict__ att_type)
{
    if (*att_type != 1) return;
    const int blk = blockIdx.x;          // 0 .. NH*SS-1
    const int bh  = blk / SS;
    const int s   = blk - bh * SS;
    const int featIdx = blk % NH;        // (bh*S + s) % nh — tile scramble

    __shared__ float qs[FF][HD];
    __shared__ float ks[FF + 1][HD];
    __shared__ float vs[FF + 1][HD];
    __shared__ float sc[FF][FF + 1];

    const int tid = threadIdx.x;
    const float* qb = q + (size_t)bh * LL * HD;
    const float* kb = k + (size_t)bh * LL * HD;
    const float* vb = v + (size_t)bh * LL * HD;
    const float* kf = k + (size_t)featIdx * LL * HD;   // feat key row (l=0)
    const float* vf = v + (size_t)featIdx * LL * HD;

    for (int i = tid; i < FF * HD; i += 256) {
        int f = i >> 7, d = i & 127;
        qs[f][d] = qb[(size_t)(1 + f * SS + s) * HD + d];
    }
    for (int i = tid; i < (FF + 1) * HD; i += 256) {
        int j = i >> 7, d = i & 127;
        if (j == 0) {
            ks[0][d] = kf[d];
            vs[0][d] = vf[d];
        } else {
            size_t l = (size_t)(1 + (j - 1) * SS + s) * HD + d;
            ks[j][d] = kb[l];
            vs[j][d] = vb[l];
        }
    }
    __syncthreads();

    // scores
    for (int p = tid; p < FF * (FF + 1); p += 256) {
        int f = p / (FF + 1);
        int j = p - f * (FF + 1);
        float a = 0.f;
#pragma unroll 8
        for (int d = 0; d < HD; d++) a += qs[f][d] * ks[j][d];
        sc[f][j] = a * 0.08838834764831844f;   // 1/sqrt(128)
    }
    __syncthreads();

    // softmax per query row (17 keys)
    if (tid < FF) {
        float mx = sc[tid][0];
#pragma unroll
        for (int j = 1; j <= FF; j++) mx = fmaxf(mx, sc[tid][j]);
        float sum = 0.f;
#pragma unroll
        for (int j = 0; j <= FF; j++) {
            float e = expf(sc[tid][j] - mx);
            sc[tid][j] = e;
            sum += e;
        }
        float inv = 1.f / sum;
#pragma unroll
        for (int j = 0; j <= FF; j++) sc[tid][j] *= inv;
    }
    __syncthreads();

    // output
    for (int i = tid; i < FF * HD; i += 256) {
        int f = i >> 7, d = i & 127;
        float a = 0.f;
#pragma unroll
        for (int j = 0; j <= FF; j++) a += sc[f][j] * vs[j][d];
        out[(size_t)bh * LL * HD + (size_t)(1 + f * SS + s) * HD + d] = a;
    }

    // feature token passes q through (only once per bh)
    if (s == 0) {
        for (int d = tid; d < HD; d += 256)
            out[(size_t)bh * LL * HD + d] = qb[d];
    }
}

// ---------------------------------------------------------------------------
// Spatial attention fallback (att_type != 1). Never taken with the fixed
// setup (att_type == 1) but implemented for completeness. Naive but correct.
// ---------------------------------------------------------------------------
__global__ void __launch_bounds__(256)
attn_spatial(const float* __restrict__ q, const float* __restrict__ k,
             const float* __restrict__ v, float* __restrict__ out,
             const int* __restrict__ att_type)
{
    if (*att_type == 1) return;
    const int bh = blockIdx.x / FF;
    const int f  = blockIdx.x - bh * FF;
    const int featIdx = blockIdx.x % NH;   // (bh*F + f) % nh — tile scramble

    const float* qb = q + (size_t)bh * LL * HD;
    const float* kb = k + (size_t)bh * LL * HD;
    const float* vb = v + (size_t)bh * LL * HD;
    const float* kf = k + (size_t)featIdx * LL * HD;
    const float* vf = v + (size_t)featIdx * LL * HD;

    __shared__ float qs[HD];
    __shared__ float sc[SS + 1];
    __shared__ float red0;

    const int tid = threadIdx.x;
    for (int s = 0; s < SS; s++) {
        int lq = 1 + f * SS + s;
        for (int d = tid; d < HD; d += 256) qs[d] = qb[(size_t)lq * HD + d];
        __syncthreads();

        for (int j = tid; j <= SS; j += 256) {
            const float* kr = (j == 0) ? kf : &kb[(size_t)(1 + f * SS + (j - 1)) * HD];
            float a = 0.f;
            for (int d = 0; d < HD; d++) a += qs[d] * kr[d];
            sc[j] = a * 0.08838834764831844f;
        }
        __syncthreads();

        if (tid == 0) {
            float mx = sc[0];
            for (int j = 1; j <= SS; j++) mx = fmaxf(mx, sc[j]);
            float sum = 0.f;
            for (int j = 0; j <= SS; j++) { float e = expf(sc[j] - mx); sc[j] = e; sum += e; }
            red0 = 1.f / sum;
        }
        __syncthreads();
        float inv = red0;

        for (int d = tid; d < HD; d += 256) {
            float a = 0.f;
            for (int j = 0; j <= SS; j++) {
                const float* vr = (j == 0) ? vf : &vb[(size_t)(1 + f * SS + (j - 1)) * HD];
                a += sc[j] * vr[d];
            }
            out[(size_t)bh * LL * HD + (size_t)lq * HD + d] = a * inv;
        }
        __syncthreads();
    }

    if (f == 0) {
        for (int d = tid; d < HD; d += 256)
            out[(size_t)bh * LL * HD + d] = qb[d];
    }
}

// ---------------------------------------------------------------------------
// Launch
// ---------------------------------------------------------------------------
extern "C" void kernel_launch(void* const* d_in, const int* in_sizes, int n_in,
                              void* d_out, int out_size)
{
    const float* x       = (const float*)d_in[0];
    const float* W_in    = (const float*)d_in[1];
    const float* b_in    = (const float*)d_in[2];
    const float* g_in    = (const float*)d_in[3];
    const float* beta_in = (const float*)d_in[4];
    const float* W_q     = (const float*)d_in[5];
    const float* W_k     = (const float*)d_in[6];
    const float* W_v     = (const float*)d_in[7];
    const float* g_out_p = (const float*)d_in[8];
    const float* beta_out= (const float*)d_in[9];
    const float* W_out   = (const float*)d_in[10];
    const float* b_out   = (const float*)d_in[11];
    const int*   att_type= (const int*)d_in[12];
    float* out = (float*)d_out;

    float *p_tmp0, *p_xln, *p_q, *p_k, *p_v, *p_attn;
    cudaGetSymbolAddress((void**)&p_tmp0, g_tmp0);
    cudaGetSymbolAddress((void**)&p_xln,  g_xln);
    cudaGetSymbolAddress((void**)&p_q,    g_q);
    cudaGetSymbolAddress((void**)&p_k,    g_k);
    cudaGetSymbolAddress((void**)&p_v,    g_v);
    cudaGetSymbolAddress((void**)&p_attn, g_attn);

    dim3 gg(DD / BN, (MM + BM - 1) / BM);   // (8, 197)

    // 1) tmp0 = x @ W_in + b_in
    gemm_kernel<0><<<gg, 256>>>(x, W_in, b_in, p_tmp0, MM);
    // 2) xln = LN(tmp0)
    ln_kernel<0><<<MM, 256>>>(p_tmp0, g_in, beta_in, p_xln);
    // 3) q/k/v head-split GEMMs
    gemm_kernel<1><<<gg, 256>>>(p_xln, W_q, nullptr, p_q, MM);
    gemm_kernel<1><<<gg, 256>>>(p_xln, W_k, nullptr, p_k, MM);
    gemm_kernel<1><<<gg, 256>>>(p_xln, W_v, nullptr, p_v, MM);
    // 4) attention (device-side dispatch on att_type)
    attn_temporal<<<NH * SS, 256>>>(p_q, p_k, p_v, p_attn, att_type);
    attn_spatial <<<NH * FF, 256>>>(p_q, p_k, p_v, p_attn, att_type);
    // 5) tmp0 = LN(merge_heads(attn))
    ln_kernel<1><<<MM, 256>>>(p_attn, g_out_p, beta_out, p_tmp0);
    // 6) out = tmp0 @ W_out + b_out
    gemm_kernel<0><<<gg, 256>>>(p_tmp0, W_out, b_out, out, MM);
}

// round 4
// speedup vs baseline: 3.9602x; 3.9602x over previous
#include <cuda_runtime.h>
#include <cuda_fp16.h>
#include <cstdint>
#include <math.h>

// Problem constants
#define NB   8
#define FF   16
#define SS   196
#define DD   1024
#define HH   8
#define HD   128
#define LL   (1 + FF * SS)      // 3137
#define MM   (NB * LL)          // 25096
#define NH   (NB * HH)          // 64

// ---------------------------------------------------------------------------
// Scratch (__device__ globals — allocation-free rule)
// ---------------------------------------------------------------------------
__device__ __half g_xh [(size_t)MM * DD];   // fp16 input to GEMM1; reused for LN2 out
__device__ __half g_lnh[(size_t)MM * DD];   // fp16 LN1 out
__device__ float g_tmp0[(size_t)MM * DD];
__device__ float g_q   [(size_t)MM * DD];
__device__ float g_k   [(size_t)MM * DD];
__device__ float g_v   [(size_t)MM * DD];
__device__ float g_attn[(size_t)MM * DD];
__device__ __half g_wt[5][(size_t)DD * DD]; // transposed fp16 weights [n][k]

// ---------------------------------------------------------------------------
// PTX helpers (baseline sm_80 features only — no tcgen05 on this target)
// ---------------------------------------------------------------------------
__device__ __forceinline__ uint32_t smem_u32(const void* p) {
    uint32_t a;
    asm("{ .reg .u64 t; cvta.to.shared.u64 t, %1; cvt.u32.u64 %0, t; }" : "=r"(a) : "l"(p));
    return a;
}
#define CP_ASYNC16(dst, src) \
    asm volatile("cp.async.cg.shared.global [%0], [%1], 16;" :: "r"(dst), "l"(src))
#define CP_COMMIT() asm volatile("cp.async.commit_group;" ::: "memory")
#define CP_WAIT(n)  asm volatile("cp.async.wait_group %0;" :: "n"(n) : "memory")

__device__ __forceinline__ void ldsm_x4(uint32_t* r, uint32_t addr) {
    asm volatile("ldmatrix.sync.aligned.m8n8.x4.shared.b16 {%0,%1,%2,%3}, [%4];"
                 : "=r"(r[0]), "=r"(r[1]), "=r"(r[2]), "=r"(r[3]) : "r"(addr));
}
__device__ __forceinline__ void ldsm_x2(uint32_t* r, uint32_t addr) {
    asm volatile("ldmatrix.sync.aligned.m8n8.x2.shared.b16 {%0,%1}, [%2];"
                 : "=r"(r[0]), "=r"(r[1]) : "r"(addr));
}
__device__ __forceinline__ void mma16816(float* c, const uint32_t* a, const uint32_t* b) {
    asm volatile(
        "mma.sync.aligned.m16n8k16.row.col.f32.f16.f16.f32 "
        "{%0,%1,%2,%3}, {%4,%5,%6,%7}, {%8,%9}, {%0,%1,%2,%3};"
        : "+f"(c[0]), "+f"(c[1]), "+f"(c[2]), "+f"(c[3])
        : "r"(a[0]), "r"(a[1]), "r"(a[2]), "r"(a[3]), "r"(b[0]), "r"(b[1]));
}

// ---------------------------------------------------------------------------
// fp16 mma.sync GEMM: C[M,1024] = A[M,1024] @ Wt[1024,1024]^T
//   A row-major fp16, Wt[n][k] fp16 (k contiguous).
// MODE 0: fp32 row-major out + bias.   MODE 1: fp32 head-split scatter.
// CTA 128x128x32, 8 warps (2x4), warp tile 64x32, 4-stage cp.async.
// ---------------------------------------------------------------------------
#define BK      32
#define NSTAGE  4
#define APAD    40                        // halves; 80-byte row stride
#define TILE_H  (128 * APAD)              // halves per A (or B) tile
#define STAGE_H (2 * TILE_H)
#define GEMM_SMEM (NSTAGE * STAGE_H * 2)  // 81920 bytes
#define KCH     32                        // 1024 / 32 chunks

template<int MODE>
__global__ void __launch_bounds__(256)
gemm_mma(const __half* __restrict__ A, const __half* __restrict__ B,
         const float* __restrict__ bias, float* __restrict__ C)
{
    extern __shared__ __half sm[];
    const uint32_t smem_base = smem_u32(sm);
    const int tid  = threadIdx.x;
    const int wid  = tid >> 5;
    const int lane = tid & 31;
    const int warp_m = wid >> 2;          // 0..1  -> 64 rows
    const int warp_n = wid & 3;           // 0..3  -> 32 cols
    const int bm = blockIdx.y * 128;
    const int bn = blockIdx.x * 128;

    // load indices for cp.async (each thread: 2 A pieces + 2 B pieces)
    const int lrow = tid >> 2;            // 0..63
    const int lkq  = (tid & 3) * 8;       // 0,8,16,24

    float c[4][4][4];
#pragma unroll
    for (int i = 0; i < 4; i++)
#pragma unroll
        for (int j = 0; j < 4; j++)
#pragma unroll
            for (int r = 0; r < 4; r++) c[i][j][r] = 0.f;

    // --- prologue: stages 0..2 ------------------------------------------
#pragma unroll
    for (int s = 0; s < NSTAGE - 1; s++) {
        const int kk = s * BK;
        const uint32_t abase = smem_base + s * STAGE_H * 2;
        const uint32_t bbase = abase + TILE_H * 2;
#pragma unroll
        for (int i = 0; i < 2; i++) {
            int row = lrow + i * 64;
            int gr  = bm + row; if (gr >= MM) gr = MM - 1;
            CP_ASYNC16(abase + (row * APAD + lkq) * 2, A + (size_t)gr * DD + kk + lkq);
            CP_ASYNC16(bbase + (row * APAD + lkq) * 2, B + (size_t)(bn + row) * DD + kk + lkq);
        }
        CP_COMMIT();
    }

    // --- main loop -------------------------------------------------------
    for (int kc = 0; kc < KCH; kc++) {
        CP_WAIT(NSTAGE - 2);
        __syncthreads();

        // issue loads for chunk kc+3
        {
            const int ld = kc + NSTAGE - 1;
            if (ld < KCH) {
                const int s = ld & (NSTAGE - 1);
                const int kk = ld * BK;
                const uint32_t abase = smem_base + s * STAGE_H * 2;
                const uint32_t bbase = abase + TILE_H * 2;
#pragma unroll
                for (int i = 0; i < 2; i++) {
                    int row = lrow + i * 64;
                    int gr  = bm + row; if (gr >= MM) gr = MM - 1;
                    CP_ASYNC16(abase + (row * APAD + lkq) * 2, A + (size_t)gr * DD + kk + lkq);
                    CP_ASYNC16(bbase + (row * APAD + lkq) * 2, B + (size_t)(bn + row) * DD + kk + lkq);
                }
            }
            CP_COMMIT();
        }

        // compute chunk kc
        const int s = kc & (NSTAGE - 1);
        const uint32_t abase = smem_base + s * STAGE_H * 2;
        const uint32_t bbase = abase + TILE_H * 2;
        const uint32_t arow = abase + ((warp_m * 64 + (lane & 15)) * APAD) * 2;
        const uint32_t brow = bbase + ((warp_n * 32 + (lane & 7)) * APAD) * 2;
#pragma unroll
        for (int ks = 0; ks < 2; ks++) {
            uint32_t af[4][4], bf[4][2];
#pragma unroll
            for (int mt = 0; mt < 4; mt++)
                ldsm_x4(af[mt], arow + (mt * 16 * APAD + ks * 16 + (lane >> 4) * 8) * 2);
#pragma unroll
            for (int nt = 0; nt < 4; nt++)
                ldsm_x2(bf[nt], brow + (nt * 8 * APAD + ks * 16 + ((lane >> 3) & 1) * 8) * 2);
#pragma unroll
            for (int mt = 0; mt < 4; mt++)
#pragma unroll
                for (int nt = 0; nt < 4; nt++)
                    mma16816(c[mt][nt], af[mt], bf[nt]);
        }
        __syncthreads();
    }

    // --- epilogue: fragment regs -> GMEM --------------------------------
    const int rfrag = lane >> 2;          // 0..7
    const int cfrag = (lane & 3) * 2;     // 0,2,4,6
#pragma unroll
    for (int mt = 0; mt < 4; mt++) {
        const int rm0 = bm + warp_m * 64 + mt * 16 + rfrag;
#pragma unroll
        for (int half = 0; half < 2; half++) {
            const int rm = rm0 + half * 8;
            if (rm >= MM) continue;
#pragma unroll
            for (int nt = 0; nt < 4; nt++) {
                const int cn = bn + warp_n * 32 + nt * 8 + cfrag;
                const float v0 = c[mt][nt][half * 2 + 0];
                const float v1 = c[mt][nt][half * 2 + 1];
                if (MODE == 0) {
                    C[(size_t)rm * DD + cn]     = v0 + bias[cn];
                    C[(size_t)rm * DD + cn + 1] = v1 + bias[cn + 1];
                } else {
                    const int b_ = rm / LL;
                    const int l_ = rm - b_ * LL;
                    const int h  = cn >> 7;
                    const int d  = cn & 127;   // d, d+1 stay within head (cn even)
                    float* dst = C + (((size_t)(b_ * HH + h)) * LL + l_) * HD + d;
                    dst[0] = v0;
                    dst[1] = v1;
                }
            }
        }
    }
}

// ---------------------------------------------------------------------------
// fp32 -> fp16 conversion
// ---------------------------------------------------------------------------
__global__ void __launch_bounds__(256)
conv_half(const float* __restrict__ in, __half* __restrict__ out)
{
    const size_t row = blockIdx.x;
    const int tid = threadIdx.x;
#pragma unroll
    for (int i = 0; i < 4; i++) {
        int cidx = i * 256 + tid;
        out[row * DD + cidx] = __float2half(in[row * DD + cidx]);
    }
}

// Weight transpose: W[k][n] fp32 -> Wt[n][k] fp16
__global__ void __launch_bounds__(256)
conv_w(const float* __restrict__ W, __half* __restrict__ Wt)
{
    __shared__ float tile[32][33];
    const int n0 = blockIdx.x * 32, k0 = blockIdx.y * 32;
    const int tx = threadIdx.x & 31, ty = threadIdx.x >> 5;   // 32 x 8
#pragma unroll
    for (int i = ty; i < 32; i += 8)
        tile[i][tx] = W[(size_t)(k0 + i) * DD + n0 + tx];
    __syncthreads();
#pragma unroll
    for (int i = ty; i < 32; i += 8)
        Wt[(size_t)(n0 + i) * DD + k0 + tx] = __float2half(tile[tx][i]);
}

// ---------------------------------------------------------------------------
// LayerNorm over D=1024, fp16 output.
// GATHER=0: row-major in. GATHER=1: head-merge gather from (nh, L, HD).
// ---------------------------------------------------------------------------
template<int GATHER>
__global__ void __launch_bounds__(256)
ln_half(const float* __restrict__ in, const float* __restrict__ g,
        const float* __restrict__ beta, __half* __restrict__ out)
{
    const int row = blockIdx.x;
    const int tid = threadIdx.x;
    int b_ = 0, l_ = 0;
    if (GATHER) { b_ = row / LL; l_ = row - b_ * LL; }

    float v[4];
    float s = 0.f, ss = 0.f;
#pragma unroll
    for (int i = 0; i < 4; i++) {
        int cidx = i * 256 + tid;
        float x;
        if (GATHER) {
            int h = cidx >> 7, d = cidx & 127;
            x = in[(((size_t)(b_ * HH + h)) * LL + l_) * HD + d];
        } else {
            x = in[(size_t)row * DD + cidx];
        }
        v[i] = x; s += x; ss += x * x;
    }

    __shared__ float rs[32], rss[32];
#pragma unroll
    for (int o = 16; o > 0; o >>= 1) {
        s  += __shfl_xor_sync(0xffffffffu, s,  o);
        ss += __shfl_xor_sync(0xffffffffu, ss, o);
    }
    int warp = tid >> 5, lane = tid & 31;
    if (lane == 0) { rs[warp] = s; rss[warp] = ss; }
    __syncthreads();
    if (warp == 0) {
        float s2  = (lane < 8) ? rs[lane]  : 0.f;
        float ss2 = (lane < 8) ? rss[lane] : 0.f;
#pragma unroll
        for (int o = 4; o > 0; o >>= 1) {
            s2  += __shfl_xor_sync(0xffffffffu, s2,  o);
            ss2 += __shfl_xor_sync(0xffffffffu, ss2, o);
        }
        if (lane == 0) { rs[0] = s2; rss[0] = ss2; }
    }
    __syncthreads();
    s = rs[0]; ss = rss[0];

    float mean = s * (1.f / 1024.f);
    float var  = ss * (1.f / 1024.f) - mean * mean;
    float rstd = rsqrtf(var + 1e-5f);

#pragma unroll
    for (int i = 0; i < 4; i++) {
        int cidx = i * 256 + tid;
        out[(size_t)row * DD + cidx] =
            __float2half((v[i] - mean) * rstd * g[cidx] + beta[cidx]);
    }
}

// ---------------------------------------------------------------------------
// Attention (verified correct in R1, incl. the jnp.tile head-scramble)
// ---------------------------------------------------------------------------
__global__ void __launch_bounds__(256)
attn_temporal(const float* __restrict__ q, const float* __restrict__ k,
              const float* __restrict__ v, float* __restrict__ out,
              const int* __restrict__ att_type)
{
    if (*att_type != 1) return;
    const int blk = blockIdx.x;
    const int bh  = blk / SS;
    const int s   = blk - bh * SS;
    const int featIdx = blk % NH;

    __shared__ float qs[FF][HD];
    __shared__ float ks[FF + 1][HD];
    __shared__ float vs[FF + 1][HD];
    __shared__ float sc[FF][FF + 1];

    const int tid = threadIdx.x;
    const float* qb = q + (size_t)bh * LL * HD;
    const float* kb = k + (size_t)bh * LL * HD;
    const float* vb = v + (size_t)bh * LL * HD;
    const float* kf = k + (size_t)featIdx * LL * HD;
    const float* vf = v + (size_t)featIdx * LL * HD;

    for (int i = tid; i < FF * HD; i += 256) {
        int f = i >> 7, d = i & 127;
        qs[f][d] = qb[(size_t)(1 + f * SS + s) * HD + d];
    }
    for (int i = tid; i < (FF + 1) * HD; i += 256) {
        int j = i >> 7, d = i & 127;
        if (j == 0) { ks[0][d] = kf[d]; vs[0][d] = vf[d]; }
        else {
            size_t l = (size_t)(1 + (j - 1) * SS + s) * HD + d;
            ks[j][d] = kb[l];
            vs[j][d] = vb[l];
        }
    }
    __syncthreads();

    for (int p = tid; p < FF * (FF + 1); p += 256) {
        int f = p / (FF + 1);
        int j = p - f * (FF + 1);
        float a = 0.f;
#pragma unroll 8
        for (int d = 0; d < HD; d++) a += qs[f][d] * ks[j][d];
        sc[f][j] = a * 0.08838834764831844f;
    }
    __syncthreads();

    if (tid < FF) {
        float mx = sc[tid][0];
#pragma unroll
        for (int j = 1; j <= FF; j++) mx = fmaxf(mx, sc[tid][j]);
        float sum = 0.f;
#pragma unroll
        for (int j = 0; j <= FF; j++) {
            float e = expf(sc[tid][j] - mx);
            sc[tid][j] = e; sum += e;
        }
        float inv = 1.f / sum;
#pragma unroll
        for (int j = 0; j <= FF; j++) sc[tid][j] *= inv;
    }
    __syncthreads();

    for (int i = tid; i < FF * HD; i += 256) {
        int f = i >> 7, d = i & 127;
        float a = 0.f;
#pragma unroll
        for (int j = 0; j <= FF; j++) a += sc[f][j] * vs[j][d];
        out[(size_t)bh * LL * HD + (size_t)(1 + f * SS + s) * HD + d] = a;
    }
    if (s == 0) {
        for (int d = tid; d < HD; d += 256)
            out[(size_t)bh * LL * HD + d] = qb[d];
    }
}

__global__ void __launch_bounds__(256)
attn_spatial(const float* __restrict__ q, const float* __restrict__ k,
             const float* __restrict__ v, float* __restrict__ out,
             const int* __restrict__ att_type)
{
    if (*att_type == 1) return;
    const int bh = blockIdx.x / FF;
    const int f  = blockIdx.x - bh * FF;
    const int featIdx = blockIdx.x % NH;

    const float* qb = q + (size_t)bh * LL * HD;
    const float* kb = k + (size_t)bh * LL * HD;
    const float* vb = v + (size_t)bh * LL * HD;
    const float* kf = k + (size_t)featIdx * LL * HD;
    const float* vf = v + (size_t)featIdx * LL * HD;

    __shared__ float qs[HD];
    __shared__ float sc[SS + 1];
    __shared__ float red0;

    const int tid = threadIdx.x;
    for (int s = 0; s < SS; s++) {
        int lq = 1 + f * SS + s;
        for (int d = tid; d < HD; d += 256) qs[d] = qb[(size_t)lq * HD + d];
        __syncthreads();

        for (int j = tid; j <= SS; j += 256) {
            const float* kr = (j == 0) ? kf : &kb[(size_t)(1 + f * SS + (j - 1)) * HD];
            float a = 0.f;
            for (int d = 0; d < HD; d++) a += qs[d] * kr[d];
            sc[j] = a * 0.08838834764831844f;
        }
        __syncthreads();

        if (tid == 0) {
            float mx = sc[0];
            for (int j = 1; j <= SS; j++) mx = fmaxf(mx, sc[j]);
            float sum = 0.f;
            for (int j = 0; j <= SS; j++) { float e = expf(sc[j] - mx); sc[j] = e; sum += e; }
            red0 = 1.f / sum;
        }
        __syncthreads();
        float inv = red0;

        for (int d = tid; d < HD; d += 256) {
            float a = 0.f;
            for (int j = 0; j <= SS; j++) {
                const float* vr = (j == 0) ? vf : &vb[(size_t)(1 + f * SS + (j - 1)) * HD];
                a += sc[j] * vr[d];
            }
            out[(size_t)bh * LL * HD + (size_t)lq * HD + d] = a * inv;
        }
        __syncthreads();
    }
    if (f == 0) {
        for (int d = tid; d < HD; d += 256)
            out[(size_t)bh * LL * HD + d] = qb[d];
    }
}

// ---------------------------------------------------------------------------
// Launch
// ---------------------------------------------------------------------------
extern "C" void kernel_launch(void* const* d_in, const int* in_sizes, int n_in,
                              void* d_out, int out_size)
{
    const float* x       = (const float*)d_in[0];
    const float* W_in    = (const float*)d_in[1];
    const float* b_in    = (const float*)d_in[2];
    const float* g_in    = (const float*)d_in[3];
    const float* beta_in = (const float*)d_in[4];
    const float* W_q     = (const float*)d_in[5];
    const float* W_k     = (const float*)d_in[6];
    const float* W_v     = (const float*)d_in[7];
    const float* g_out_p = (const float*)d_in[8];
    const float* beta_out= (const float*)d_in[9];
    const float* W_out   = (const float*)d_in[10];
    const float* b_out   = (const float*)d_in[11];
    const int*   att_type= (const int*)d_in[12];
    float* out = (float*)d_out;

    __half *p_xh, *p_lnh, *p_wt;
    float *p_tmp0, *p_q, *p_k, *p_v, *p_attn;
    cudaGetSymbolAddress((void**)&p_xh,   g_xh);
    cudaGetSymbolAddress((void**)&p_lnh,  g_lnh);
    cudaGetSymbolAddress((void**)&p_tmp0, g_tmp0);
    cudaGetSymbolAddress((void**)&p_q,    g_q);
    cudaGetSymbolAddress((void**)&p_k,    g_k);
    cudaGetSymbolAddress((void**)&p_v,    g_v);
    cudaGetSymbolAddress((void**)&p_attn, g_attn);
    cudaGetSymbolAddress((void**)&p_wt,   g_wt);
    __half* wt0 = p_wt;
    __half* wt1 = p_wt + (size_t)1 * DD * DD;
    __half* wt2 = p_wt + (size_t)2 * DD * DD;
    __half* wt3 = p_wt + (size_t)3 * DD * DD;
    __half* wt4 = p_wt + (size_t)4 * DD * DD;

    cudaFuncSetAttribute(gemm_mma<0>, cudaFuncAttributeMaxDynamicSharedMemorySize, GEMM_SMEM);
    cudaFuncSetAttribute(gemm_mma<1>, cudaFuncAttributeMaxDynamicSharedMemorySize, GEMM_SMEM);

    dim3 wgrid(32, 32);
    conv_w<<<wgrid, 256>>>(W_in,  wt0);
    conv_w<<<wgrid, 256>>>(W_q,   wt1);
    conv_w<<<wgrid, 256>>>(W_k,   wt2);
    conv_w<<<wgrid, 256>>>(W_v,   wt3);
    conv_w<<<wgrid, 256>>>(W_out, wt4);
    conv_half<<<MM, 256>>>(x, p_xh);

    dim3 gg(DD / 128, (MM + 127) / 128);   // (8, 197)

    gemm_mma<0><<<gg, 256, GEMM_SMEM>>>(p_xh, wt0, b_in, p_tmp0);
    ln_half<0><<<MM, 256>>>(p_tmp0, g_in, beta_in, p_lnh);
    gemm_mma<1><<<gg, 256, GEMM_SMEM>>>(p_lnh, wt1, b_in, p_q);
    gemm_mma<1><<<gg, 256, GEMM_SMEM>>>(p_lnh, wt2, b_in, p_k);
    gemm_mma<1><<<gg, 256, GEMM_SMEM>>>(p_lnh, wt3, b_in, p_v);

    attn_temporal<<<NH * SS, 256>>>(p_q, p_k, p_v, p_attn, att_type);
    attn_spatial <<<NH * FF, 256>>>(p_q, p_k, p_v, p_attn, att_type);

    ln_half<1><<<MM, 256>>>(p_attn, g_out_p, beta_out, p_xh);
    gemm_mma<0><<<gg, 256, GEMM_SMEM>>>(p_xh, wt4, b_out, out);
}